// round 4
// baseline (speedup 1.0000x reference)
#include <cuda_runtime.h>
#include <cuda_bf16.h>
#include <cstdint>
#include <math.h>

#define T_  2048
#define D_  2048
#define H_  16
#define HD_ 128

typedef __nv_bfloat16 bf16;

// ---------------------------------------------------------------------------
// Scratch (allocation-free rule: __device__ globals)
// ---------------------------------------------------------------------------
__device__ float g_Q[T_ * D_];
__device__ float g_K[T_ * D_];
__device__ float g_V[T_ * D_];
__device__ bf16 g_xhi[T_ * D_];
__device__ bf16 g_xlo[T_ * D_];
__device__ bf16 g_Ahi[T_ * D_];
__device__ bf16 g_Alo[T_ * D_];
__device__ bf16 g_Wthi[4][D_ * D_];   // transposed weights [N,K], hi part
__device__ bf16 g_Wtlo[4][D_ * D_];   // transposed weights [N,K], lo part

// ---------------------------------------------------------------------------
// PTX helpers (compute_103-safe: mma.sync / ldmatrix / cp.async only)
// ---------------------------------------------------------------------------
__device__ __forceinline__ uint32_t smem_u32(const void* p) {
    uint32_t a;
    asm("{ .reg .u64 t; cvta.to.shared.u64 t, %1; cvt.u32.u64 %0, t; }"
        : "=r"(a) : "l"(p));
    return a;
}

#define CPA16(dst, src) \
    asm volatile("cp.async.cg.shared.global [%0], [%1], 16;" :: "r"(dst), "l"(src) : "memory")
#define CPA_COMMIT() asm volatile("cp.async.commit_group;" ::: "memory")
#define CPA_WAIT(n)  asm volatile("cp.async.wait_group %0;" :: "n"(n) : "memory")

__device__ __forceinline__ void ldsm_x4(uint32_t* r, uint32_t addr) {
    asm volatile("ldmatrix.sync.aligned.m8n8.x4.shared.b16 {%0,%1,%2,%3}, [%4];"
                 : "=r"(r[0]), "=r"(r[1]), "=r"(r[2]), "=r"(r[3]) : "r"(addr));
}

__device__ __forceinline__ void mma_bf16(float* d, const uint32_t* a,
                                         const uint32_t* b) {
    asm volatile(
        "mma.sync.aligned.m16n8k16.row.col.f32.bf16.bf16.f32 "
        "{%0,%1,%2,%3}, {%4,%5,%6,%7}, {%8,%9}, {%0,%1,%2,%3};"
        : "+f"(d[0]), "+f"(d[1]), "+f"(d[2]), "+f"(d[3])
        : "r"(a[0]), "r"(a[1]), "r"(a[2]), "r"(a[3]), "r"(b[0]), "r"(b[1]));
}

// Packed smem layout for 64B logical rows: pairs of rows share a 128B
// super-row; SW128 XOR keeps ldmatrix conflict-free.
__device__ __forceinline__ uint32_t phys(int r, int cb) {
    return (uint32_t)((r >> 1) * 128) +
           ((((r & 1) << 6) + cb) ^ (((r >> 1) & 7) << 4));
}

// ---------------------------------------------------------------------------
// Split fp32 -> (hi, lo) bf16, row-major
// ---------------------------------------------------------------------------
__global__ __launch_bounds__(256) void split_kernel(const float* __restrict__ src,
                                                    bf16* __restrict__ hi,
                                                    bf16* __restrict__ lo)
{
    int i = blockIdx.x * 256 + threadIdx.x;
    if (i >= T_ * D_) return;
    float v = src[i];
    bf16 h = __float2bfloat16(v);
    float r = v - __bfloat162float(h);
    hi[i] = h;
    lo[i] = __float2bfloat16(r);
}

// ---------------------------------------------------------------------------
// Transpose + split all 4 weights in one launch: W[K,N] -> Thi/Tlo[N,K].
// ---------------------------------------------------------------------------
__global__ __launch_bounds__(256) void transpose_split4(
    const float* __restrict__ W0, const float* __restrict__ W1,
    const float* __restrict__ W2, const float* __restrict__ W3,
    bf16* __restrict__ ThiB, bf16* __restrict__ TloB)
{
    __shared__ float tile[32][33];
    const size_t WSZ = (size_t)D_ * D_;
    int z = blockIdx.z;
    const float* W = (z == 0) ? W0 : (z == 1) ? W1 : (z == 2) ? W2 : W3;
    bf16* Thi = ThiB + z * WSZ;
    bf16* Tlo = TloB + z * WSZ;

    int bx = blockIdx.x * 32;   // N block
    int by = blockIdx.y * 32;   // K block
    int tx = threadIdx.x;
    int ty = threadIdx.y;       // block (32, 8)
#pragma unroll
    for (int j = 0; j < 32; j += 8)
        tile[ty + j][tx] = W[(size_t)(by + ty + j) * D_ + bx + tx];
    __syncthreads();
#pragma unroll
    for (int j = 0; j < 32; j += 8) {
        float v = tile[tx][ty + j];
        bf16 h = __float2bfloat16(v);
        float r = v - __bfloat162float(h);
        size_t o = (size_t)(bx + ty + j) * D_ + by + tx;
        Thi[o] = h;
        Tlo[o] = __float2bfloat16(r);
    }
}

// ---------------------------------------------------------------------------
// HMMA GEMM: C = A @ Bt^T, split-bf16 3-MMA.
// CTA tile 128x128, BK=32, 3-stage cp.async (96KB smem -> 2 CTAs/SM).
// 8 warps, 64x32 warp tiles. blockIdx.z selects fused QKV outputs.
// ---------------------------------------------------------------------------
#define STAGE_BYTES 32768
#define GSMEM_BYTES (3 * STAGE_BYTES)
#define NCHUNK 64

__global__ __launch_bounds__(256, 2) void gemm_hmma(
    const bf16* __restrict__ Ahi, const bf16* __restrict__ Alo,
    const bf16* __restrict__ Bhi_base, const bf16* __restrict__ Blo_base,
    float* C0, float* C1, float* C2)
{
    extern __shared__ char smem[];
    uint32_t sb = smem_u32(smem);
    const int tid  = threadIdx.x;
    const int wid  = tid >> 5;
    const int lane = tid & 31;
    const int wm = wid >> 2;          // 0..1  (64-row block)
    const int wn = wid & 3;           // 0..3  (32-col block)
    const int row0 = blockIdx.y * 128;
    const int col0 = blockIdx.x * 128;
    const size_t WSZ = (size_t)D_ * D_;
    const bf16* Bhi = Bhi_base + blockIdx.z * WSZ;
    const bf16* Blo = Blo_base + blockIdx.z * WSZ;
    float* C = (blockIdx.z == 0) ? C0 : (blockIdx.z == 1) ? C1 : C2;

    const char* base[4] = {
        (const char*)(Ahi + (size_t)row0 * D_),
        (const char*)(Alo + (size_t)row0 * D_),
        (const char*)(Bhi + (size_t)col0 * D_),
        (const char*)(Blo + (size_t)col0 * D_)
    };

    // One stage: 4 matrices x 128 rows x 64B (BK=32 bf16) = 32KB.
    auto load_stage = [&](int c, int s) {
        uint32_t st = sb + s * STAGE_BYTES;
#pragma unroll
        for (int j = 0; j < 8; j++) {
            int q = tid + (j << 8);          // 0..2047
            int m = q >> 9;                  // matrix 0..3
            int qq = q & 511;
            int r = qq >> 2;                 // row 0..127
            int cb = (qq & 3) << 4;          // 0..48
            const char* src = base[m] + (size_t)r * (D_ * 2) + c * 64 + cb;
            CPA16(st + m * 8192 + phys(r, cb), src);
        }
        CPA_COMMIT();
    };

    float acc[4][4][4];
#pragma unroll
    for (int i = 0; i < 4; i++)
#pragma unroll
        for (int j = 0; j < 4; j++)
#pragma unroll
            for (int q = 0; q < 4; q++) acc[i][j][q] = 0.0f;

    load_stage(0, 0);
    load_stage(1, 1);
    load_stage(2, 2);

    int s = 0;
    for (int c = 0; c < NCHUNK; c++) {
        if (c <= NCHUNK - 3) CPA_WAIT(2);
        else if (c == NCHUNK - 2) CPA_WAIT(1);
        else CPA_WAIT(0);
        __syncthreads();

        uint32_t st   = sb + s * STAGE_BYTES;
        uint32_t sAhi = st;
        uint32_t sAlo = st + 8192;
        uint32_t sBhi = st + 16384;
        uint32_t sBlo = st + 24576;

#pragma unroll
        for (int ks = 0; ks < 2; ks++) {
            // B fragments: 2 x n16 loads -> 4 n8 tiles, hi + lo.
            uint32_t bh[8], bl[8];
            int bcb = ks * 32 + ((lane >> 3) & 1) * 16;
#pragma unroll
            for (int jp = 0; jp < 2; jp++) {
                int row = wn * 32 + jp * 16 + ((lane >> 4) & 1) * 8 + (lane & 7);
                uint32_t off = phys(row, bcb);
                ldsm_x4(&bh[jp * 4], sBhi + off);
                ldsm_x4(&bl[jp * 4], sBlo + off);
            }
            int acb = ks * 32 + ((lane >> 4) & 1) * 16;
#pragma unroll
            for (int i = 0; i < 4; i++) {
                uint32_t ah[4], al[4];
                int row = wm * 64 + i * 16 + (lane & 15);
                uint32_t off = phys(row, acb);
                ldsm_x4(ah, sAhi + off);
                ldsm_x4(al, sAlo + off);
#pragma unroll
                for (int j = 0; j < 4; j++) {
                    mma_bf16(acc[i][j], ah, &bh[j * 2]);
                    mma_bf16(acc[i][j], al, &bh[j * 2]);
                    mma_bf16(acc[i][j], ah, &bl[j * 2]);
                }
            }
        }
        __syncthreads();
        if (c + 3 < NCHUNK) load_stage(c + 3, s);
        s = (s == 2) ? 0 : s + 1;
    }

    // Epilogue: direct register -> gmem (float2 per fragment row).
    const int g = lane >> 2;
    const int t = lane & 3;
#pragma unroll
    for (int i = 0; i < 4; i++) {
#pragma unroll
        for (int j = 0; j < 4; j++) {
            int row = row0 + wm * 64 + i * 16 + g;
            int col = col0 + wn * 32 + j * 8 + 2 * t;
            *(float2*)&C[(size_t)row * D_ + col] =
                make_float2(acc[i][j][0], acc[i][j][1]);
            *(float2*)&C[(size_t)(row + 8) * D_ + col] =
                make_float2(acc[i][j][2], acc[i][j][3]);
        }
    }
}

// ---------------------------------------------------------------------------
// RoPE (in-place) on Q and K.
// ---------------------------------------------------------------------------
__global__ __launch_bounds__(256) void rope_kernel(float* __restrict__ Q,
                                                   float* __restrict__ K,
                                                   const float* __restrict__ sin_t,
                                                   const float* __restrict__ cos_t)
{
    int idx = blockIdx.x * blockDim.x + threadIdx.x;
    if (idx >= T_ * H_ * 64) return;
    int d = idx & 63;
    int h = (idx >> 6) & (H_ - 1);
    int t = idx >> 10;
    int base = t * D_ + h * HD_;

    float s1 = sin_t[t * HD_ + d];
    float c1 = cos_t[t * HD_ + d];
    float s2 = sin_t[t * HD_ + d + 64];
    float c2 = cos_t[t * HD_ + d + 64];

    float q1 = Q[base + d];
    float q2 = Q[base + d + 64];
    Q[base + d]      = q1 * c1 - q2 * s1;
    Q[base + d + 64] = q2 * c2 + q1 * s2;

    float k1 = K[base + d];
    float k2 = K[base + d + 64];
    K[base + d]      = k1 * c1 - k2 * s1;
    K[base + d + 64] = k2 * c2 + k1 * s2;
}

// ---------------------------------------------------------------------------
// Flash-style attention with causal + same-doc mask.
// Epilogue writes bf16 hi/lo directly (feeds O-proj GEMM).
// ---------------------------------------------------------------------------
#define BM 64
#define BN 64
#define LDK 132
#define LDP 65

__global__ __launch_bounds__(256) void attn_kernel(const float* __restrict__ Q,
                                                   const float* __restrict__ K,
                                                   const float* __restrict__ V,
                                                   const int* __restrict__ doc,
                                                   bf16* __restrict__ Ahi,
                                                   bf16* __restrict__ Alo)
{
    extern __shared__ float sm[];
    float* Qs = sm;
    float* Ks = Qs + BM * HD_;
    float* Vs = Ks + BN * LDK;
    float* Ps = Vs + BN * HD_;
    float* rescale = Ps + BM * LDP;
    float* lrow = rescale + BM;
    __shared__ int qdoc[BM];
    __shared__ int kdoc[BN];

    const int h = blockIdx.y;
    const int qt = blockIdx.x;
    const int qbase = qt * BM;
    const int tid = threadIdx.x;

    const float scale = 0.08838834764831845f;

    for (int i = tid; i < BM * HD_ / 4; i += 256) {
        int r = i >> 5;
        int c4 = (i & 31) << 2;
        float4 v = *(const float4*)&Q[(qbase + r) * D_ + h * HD_ + c4];
        v.x *= scale; v.y *= scale; v.z *= scale; v.w *= scale;
        *(float4*)&Qs[r * HD_ + c4] = v;
    }
    if (tid < BM) qdoc[tid] = doc[qbase + tid];

    const int sr = tid >> 4;
    const int sc = tid & 15;
    const int rg = tid >> 4;
    const int c0 = (tid & 15) << 3;
    const int srow  = tid >> 2;   // softmax: 4 threads per row
    const int spart = tid & 3;

    float acc[4][8];
#pragma unroll
    for (int i = 0; i < 4; i++)
#pragma unroll
        for (int j = 0; j < 8; j++) acc[i][j] = 0.0f;

    float m_i = -1e30f, l_i = 0.0f;   // replicated x4 per row

    __syncthreads();
    const int qd_first = qdoc[0];

    for (int kt = 0; kt <= qt; ++kt) {
        const int kbase = kt * BN;
        if (doc[kbase + BN - 1] < qd_first) continue;

        __syncthreads();

        for (int i = tid; i < BN * HD_ / 4; i += 256) {
            int r = i >> 5;
            int c4 = (i & 31) << 2;
            float4 kv = *(const float4*)&K[(kbase + r) * D_ + h * HD_ + c4];
            float4 vv = *(const float4*)&V[(kbase + r) * D_ + h * HD_ + c4];
            *(float4*)&Ks[r * LDK + c4] = kv;
            *(float4*)&Vs[r * HD_ + c4] = vv;
        }
        if (tid < BN) kdoc[tid] = doc[kbase + tid];
        __syncthreads();

        float s[4][4];
#pragma unroll
        for (int i = 0; i < 4; i++)
#pragma unroll
            for (int j = 0; j < 4; j++) s[i][j] = 0.0f;

        for (int d4 = 0; d4 < HD_; d4 += 4) {
            float4 qv[4], kv[4];
#pragma unroll
            for (int i = 0; i < 4; i++)
                qv[i] = *(float4*)&Qs[(sr + 16 * i) * HD_ + d4];
#pragma unroll
            for (int j = 0; j < 4; j++)
                kv[j] = *(float4*)&Ks[(sc + 16 * j) * LDK + d4];
#pragma unroll
            for (int i = 0; i < 4; i++)
#pragma unroll
                for (int j = 0; j < 4; j++) {
                    s[i][j] = fmaf(qv[i].x, kv[j].x, s[i][j]);
                    s[i][j] = fmaf(qv[i].y, kv[j].y, s[i][j]);
                    s[i][j] = fmaf(qv[i].z, kv[j].z, s[i][j]);
                    s[i][j] = fmaf(qv[i].w, kv[j].w, s[i][j]);
                }
        }

#pragma unroll
        for (int i = 0; i < 4; i++) {
            int r = sr + 16 * i;
            int gq = qbase + r;
            int dq = qdoc[r];
#pragma unroll
            for (int j = 0; j < 4; j++) {
                int c = sc + 16 * j;
                int gk = kbase + c;
                bool ok = (gk <= gq) && (kdoc[c] == dq);
                Ps[r * LDP + c] = ok ? s[i][j] : -1e30f;
            }
        }
        __syncthreads();

        // Online softmax: 4 threads per row, shuffle-combined.
        {
            float* prow = &Ps[srow * LDP + spart * 16];
            float mrow = -1e30f;
#pragma unroll
            for (int j = 0; j < 16; j++) mrow = fmaxf(mrow, prow[j]);
            mrow = fmaxf(mrow, __shfl_xor_sync(0xffffffffu, mrow, 1));
            mrow = fmaxf(mrow, __shfl_xor_sync(0xffffffffu, mrow, 2));
            float mnew = fmaxf(m_i, mrow);
            float resc = __expf(m_i - mnew);
            float sum = 0.0f;
#pragma unroll
            for (int j = 0; j < 16; j++) {
                float sv = prow[j];
                float p = (sv <= -1e29f) ? 0.0f : __expf(sv - mnew);
                prow[j] = p;
                sum += p;
            }
            sum += __shfl_xor_sync(0xffffffffu, sum, 1);
            sum += __shfl_xor_sync(0xffffffffu, sum, 2);
            l_i = l_i * resc + sum;
            m_i = mnew;
            if (spart == 0) rescale[srow] = resc;
        }
        __syncthreads();

#pragma unroll
        for (int i = 0; i < 4; i++) {
            float resc = rescale[rg + 16 * i];
#pragma unroll
            for (int j = 0; j < 8; j++) acc[i][j] *= resc;
        }

        for (int j = 0; j < BN; ++j) {
            float4 v0 = *(float4*)&Vs[j * HD_ + c0];
            float4 v1 = *(float4*)&Vs[j * HD_ + c0 + 4];
#pragma unroll
            for (int i = 0; i < 4; i++) {
                float p = Ps[(rg + 16 * i) * LDP + j];
                acc[i][0] = fmaf(p, v0.x, acc[i][0]);
                acc[i][1] = fmaf(p, v0.y, acc[i][1]);
                acc[i][2] = fmaf(p, v0.z, acc[i][2]);
                acc[i][3] = fmaf(p, v0.w, acc[i][3]);
                acc[i][4] = fmaf(p, v1.x, acc[i][4]);
                acc[i][5] = fmaf(p, v1.y, acc[i][5]);
                acc[i][6] = fmaf(p, v1.z, acc[i][6]);
                acc[i][7] = fmaf(p, v1.w, acc[i][7]);
            }
        }
    }

    if (spart == 0) lrow[srow] = l_i;
    __syncthreads();

    // Epilogue: normalize and write split-bf16 directly.
#pragma unroll
    for (int i = 0; i < 4; i++) {
        int r = rg + 16 * i;
        float inv = 1.0f / lrow[r];
        bf16 h8[8], l8[8];
#pragma unroll
        for (int j = 0; j < 8; j++) {
            float v = acc[i][j] * inv;
            bf16 hv = __float2bfloat16(v);
            h8[j] = hv;
            l8[j] = __float2bfloat16(v - __bfloat162float(hv));
        }
        size_t idx = (size_t)(qbase + r) * D_ + h * HD_ + c0;
        *(uint4*)&Ahi[idx] = *(uint4*)h8;
        *(uint4*)&Alo[idx] = *(uint4*)l8;
    }
}

// ---------------------------------------------------------------------------
// Launch
// ---------------------------------------------------------------------------
extern "C" void kernel_launch(void* const* d_in, const int* in_sizes, int n_in,
                              void* d_out, int out_size)
{
    const float* x    = (const float*)d_in[0];
    const float* Wq   = (const float*)d_in[1];
    const float* Wk   = (const float*)d_in[2];
    const float* Wv   = (const float*)d_in[3];
    const float* Wo   = (const float*)d_in[4];
    const float* sint = (const float*)d_in[5];
    const float* cost = (const float*)d_in[6];
    const int*   doc  = (const int*)d_in[7];

    float *Q, *K, *V;
    bf16 *xhi, *xlo, *Ahi, *Alo, *Wthi, *Wtlo;
    cudaGetSymbolAddress((void**)&Q, g_Q);
    cudaGetSymbolAddress((void**)&K, g_K);
    cudaGetSymbolAddress((void**)&V, g_V);
    cudaGetSymbolAddress((void**)&xhi, g_xhi);
    cudaGetSymbolAddress((void**)&xlo, g_xlo);
    cudaGetSymbolAddress((void**)&Ahi, g_Ahi);
    cudaGetSymbolAddress((void**)&Alo, g_Alo);
    cudaGetSymbolAddress((void**)&Wthi, g_Wthi);
    cudaGetSymbolAddress((void**)&Wtlo, g_Wtlo);

    const size_t WSZ = (size_t)D_ * D_;
    const int NELEM = T_ * D_;

    split_kernel<<<(NELEM + 255) / 256, 256>>>(x, xhi, xlo);
    dim3 tsGrid(D_ / 32, D_ / 32, 4), tsBlk(32, 8);
    transpose_split4<<<tsGrid, tsBlk>>>(Wq, Wk, Wv, Wo, Wthi, Wtlo);

    cudaFuncSetAttribute(gemm_hmma,
                         cudaFuncAttributeMaxDynamicSharedMemorySize, GSMEM_BYTES);

    dim3 gGridQKV(D_ / 128, T_ / 128, 3);
    gemm_hmma<<<gGridQKV, 256, GSMEM_BYTES>>>(xhi, xlo, Wthi, Wtlo, Q, K, V);

    int nrope = T_ * H_ * 64;
    rope_kernel<<<(nrope + 255) / 256, 256>>>(Q, K, sint, cost);

    size_t smem = (size_t)(BM * HD_ + BN * LDK + BN * HD_ + BM * LDP + 2 * BM)
                  * sizeof(float);
    cudaFuncSetAttribute(attn_kernel,
                         cudaFuncAttributeMaxDynamicSharedMemorySize, (int)smem);
    attn_kernel<<<dim3(T_ / BM, H_), 256, smem>>>(Q, K, V, doc, Ahi, Alo);

    dim3 gGridO(D_ / 128, T_ / 128, 1);
    gemm_hmma<<<gGridO, 256, GSMEM_BYTES>>>(Ahi, Alo, Wthi + 3 * WSZ, Wtlo + 3 * WSZ,
                                            (float*)d_out, nullptr, nullptr);
}

// round 6
// speedup vs baseline: 1.5413x; 1.5413x over previous
#include <cuda_runtime.h>
#include <cuda_bf16.h>
#include <cstdint>
#include <math.h>

#define T_  2048
#define D_  2048
#define H_  16
#define HD_ 128

typedef __nv_bfloat16 bf16;

// ---------------------------------------------------------------------------
// Scratch (allocation-free rule: __device__ globals)
// ---------------------------------------------------------------------------
__device__ float g_Q[T_ * D_];
__device__ float g_K[T_ * D_];
__device__ float g_V[T_ * D_];
__device__ bf16 g_xhi[T_ * D_];
__device__ bf16 g_xlo[T_ * D_];
__device__ bf16 g_Ahi[T_ * D_];
__device__ bf16 g_Alo[T_ * D_];
__device__ bf16 g_Wthi[4][D_ * D_];   // transposed weights [N,K], hi part
__device__ bf16 g_Wtlo[4][D_ * D_];   // transposed weights [N,K], lo part

// ---------------------------------------------------------------------------
// PTX helpers (compute_103-safe: mma.sync / ldmatrix / cp.async only)
// ---------------------------------------------------------------------------
__device__ __forceinline__ uint32_t smem_u32(const void* p) {
    uint32_t a;
    asm("{ .reg .u64 t; cvta.to.shared.u64 t, %1; cvt.u32.u64 %0, t; }"
        : "=r"(a) : "l"(p));
    return a;
}

#define CPA16(dst, src) \
    asm volatile("cp.async.cg.shared.global [%0], [%1], 16;" :: "r"(dst), "l"(src) : "memory")
#define CPA_COMMIT() asm volatile("cp.async.commit_group;" ::: "memory")
#define CPA_WAIT(n)  asm volatile("cp.async.wait_group %0;" :: "n"(n) : "memory")

__device__ __forceinline__ void ldsm_x4(uint32_t* r, uint32_t addr) {
    asm volatile("ldmatrix.sync.aligned.m8n8.x4.shared.b16 {%0,%1,%2,%3}, [%4];"
                 : "=r"(r[0]), "=r"(r[1]), "=r"(r[2]), "=r"(r[3]) : "r"(addr));
}

__device__ __forceinline__ void mma_bf16(float* d, const uint32_t* a,
                                         const uint32_t* b) {
    asm volatile(
        "mma.sync.aligned.m16n8k16.row.col.f32.bf16.bf16.f32 "
        "{%0,%1,%2,%3}, {%4,%5,%6,%7}, {%8,%9}, {%0,%1,%2,%3};"
        : "+f"(d[0]), "+f"(d[1]), "+f"(d[2]), "+f"(d[3])
        : "r"(a[0]), "r"(a[1]), "r"(a[2]), "r"(a[3]), "r"(b[0]), "r"(b[1]));
}

// ---------------------------------------------------------------------------
// Split fp32 -> (hi, lo) bf16, row-major
// ---------------------------------------------------------------------------
__global__ __launch_bounds__(256) void split_kernel(const float* __restrict__ src,
                                                    bf16* __restrict__ hi,
                                                    bf16* __restrict__ lo)
{
    int i = blockIdx.x * 256 + threadIdx.x;
    if (i >= T_ * D_) return;
    float v = src[i];
    bf16 h = __float2bfloat16(v);
    float r = v - __bfloat162float(h);
    hi[i] = h;
    lo[i] = __float2bfloat16(r);
}

// ---------------------------------------------------------------------------
// Transpose + split all 4 weights in one launch: W[K,N] -> Thi/Tlo[N,K].
// ---------------------------------------------------------------------------
__global__ __launch_bounds__(256) void transpose_split4(
    const float* __restrict__ W0, const float* __restrict__ W1,
    const float* __restrict__ W2, const float* __restrict__ W3,
    bf16* __restrict__ ThiB, bf16* __restrict__ TloB)
{
    __shared__ float tile[32][33];
    const size_t WSZ = (size_t)D_ * D_;
    int z = blockIdx.z;
    const float* W = (z == 0) ? W0 : (z == 1) ? W1 : (z == 2) ? W2 : W3;
    bf16* Thi = ThiB + z * WSZ;
    bf16* Tlo = TloB + z * WSZ;

    int bx = blockIdx.x * 32;   // N block
    int by = blockIdx.y * 32;   // K block
    int tx = threadIdx.x;
    int ty = threadIdx.y;       // block (32, 8)
#pragma unroll
    for (int j = 0; j < 32; j += 8)
        tile[ty + j][tx] = W[(size_t)(by + ty + j) * D_ + bx + tx];
    __syncthreads();
#pragma unroll
    for (int j = 0; j < 32; j += 8) {
        float v = tile[tx][ty + j];
        bf16 h = __float2bfloat16(v);
        float r = v - __bfloat162float(h);
        size_t o = (size_t)(bx + ty + j) * D_ + by + tx;
        Thi[o] = h;
        Tlo[o] = __float2bfloat16(r);
    }
}

// ---------------------------------------------------------------------------
// HMMA GEMM (R3 configuration): C = A @ Bt^T, split-bf16 3-MMA.
// CTA tile 128x128, BK=64 (128B rows), 3-stage cp.async, 192KB smem.
// 8 warps x (64x32) warp tiles. blockIdx.z selects fused QKV outputs.
// ---------------------------------------------------------------------------
#define STAGE_BYTES 65536
#define GSMEM_BYTES (3 * STAGE_BYTES)

__global__ __launch_bounds__(256) void gemm_hmma(
    const bf16* __restrict__ Ahi, const bf16* __restrict__ Alo,
    const bf16* __restrict__ Bhi_base, const bf16* __restrict__ Blo_base,
    float* C0, float* C1, float* C2)
{
    extern __shared__ char smem[];
    uint32_t sb = smem_u32(smem);
    const int tid  = threadIdx.x;
    const int wid  = tid >> 5;
    const int lane = tid & 31;
    const int wm = wid >> 2;          // 0..1  (64-row block)
    const int wn = wid & 3;           // 0..3  (32-col block)
    const int row0 = blockIdx.y * 128;
    const int col0 = blockIdx.x * 128;
    const size_t WSZ = (size_t)D_ * D_;
    const bf16* Bhi = Bhi_base + blockIdx.z * WSZ;
    const bf16* Blo = Blo_base + blockIdx.z * WSZ;
    float* C = (blockIdx.z == 0) ? C0 : (blockIdx.z == 1) ? C1 : C2;

    const char* base[4] = {
        (const char*)(Ahi + (size_t)row0 * D_),
        (const char*)(Alo + (size_t)row0 * D_),
        (const char*)(Bhi + (size_t)col0 * D_),
        (const char*)(Blo + (size_t)col0 * D_)
    };

    // One stage: 4 matrices x 128 rows x 128B (BK=64 bf16), XOR-swizzled.
    auto load_stage = [&](int c, int s) {
        uint32_t st = sb + s * STAGE_BYTES;
#pragma unroll
        for (int j = 0; j < 16; j++) {
            int m = j >> 2;
            int rem = tid + ((j & 3) << 8);
            int r = rem >> 3;
            int cb = (rem & 7) << 4;
            const char* src = base[m] + (size_t)r * (D_ * 2) + c * 128 + cb;
            uint32_t off = (uint32_t)(r * 128) + (cb ^ ((r & 7) << 4));
            CPA16(st + m * 16384 + off, src);
        }
        CPA_COMMIT();
    };

    float acc[4][4][4];
#pragma unroll
    for (int i = 0; i < 4; i++)
#pragma unroll
        for (int j = 0; j < 4; j++)
#pragma unroll
            for (int q = 0; q < 4; q++) acc[i][j][q] = 0.0f;

    load_stage(0, 0);
    load_stage(1, 1);
    load_stage(2, 2);

    for (int c = 0; c < 32; c++) {
        int s = c % 3;
        if (c <= 29) CPA_WAIT(2);
        else if (c == 30) CPA_WAIT(1);
        else CPA_WAIT(0);
        __syncthreads();

        uint32_t st   = sb + s * STAGE_BYTES;
        uint32_t sAhi = st;
        uint32_t sAlo = st + 16384;
        uint32_t sBhi = st + 32768;
        uint32_t sBlo = st + 49152;

#pragma unroll
        for (int ks = 0; ks < 4; ks++) {
            uint32_t ah[4][4], al[4][4];
#pragma unroll
            for (int i = 0; i < 4; i++) {
                int row = wm * 64 + i * 16 + (lane & 15);
                uint32_t colb = ks * 32 + ((lane >> 4) & 1) * 16;
                uint32_t off = (uint32_t)(row * 128) + (colb ^ ((row & 7) << 4));
                ldsm_x4(ah[i], sAhi + off);
                ldsm_x4(al[i], sAlo + off);
            }
            uint32_t bh[8], bl[8];
#pragma unroll
            for (int jp = 0; jp < 2; jp++) {
                int row = wn * 32 + jp * 16 + ((lane >> 4) & 1) * 8 + (lane & 7);
                uint32_t colb = ks * 32 + ((lane >> 3) & 1) * 16;
                uint32_t off = (uint32_t)(row * 128) + (colb ^ ((row & 7) << 4));
                ldsm_x4(&bh[jp * 4], sBhi + off);
                ldsm_x4(&bl[jp * 4], sBlo + off);
            }
#pragma unroll
            for (int i = 0; i < 4; i++)
#pragma unroll
                for (int j = 0; j < 4; j++) {
                    mma_bf16(acc[i][j], ah[i], &bh[j * 2]);
                    mma_bf16(acc[i][j], al[i], &bh[j * 2]);
                    mma_bf16(acc[i][j], ah[i], &bl[j * 2]);
                }
        }
        __syncthreads();
        if (c + 3 < 32) load_stage(c + 3, s);
    }

    // Epilogue: direct register -> gmem (float2 per fragment row).
    const int g = lane >> 2;
    const int t = lane & 3;
#pragma unroll
    for (int i = 0; i < 4; i++) {
#pragma unroll
        for (int j = 0; j < 4; j++) {
            int row = row0 + wm * 64 + i * 16 + g;
            int col = col0 + wn * 32 + j * 8 + 2 * t;
            *(float2*)&C[(size_t)row * D_ + col] =
                make_float2(acc[i][j][0], acc[i][j][1]);
            *(float2*)&C[(size_t)(row + 8) * D_ + col] =
                make_float2(acc[i][j][2], acc[i][j][3]);
        }
    }
}

// ---------------------------------------------------------------------------
// RoPE (in-place) on Q and K.
// ---------------------------------------------------------------------------
__global__ __launch_bounds__(256) void rope_kernel(float* __restrict__ Q,
                                                   float* __restrict__ K,
                                                   const float* __restrict__ sin_t,
                                                   const float* __restrict__ cos_t)
{
    int idx = blockIdx.x * blockDim.x + threadIdx.x;
    if (idx >= T_ * H_ * 64) return;
    int d = idx & 63;
    int h = (idx >> 6) & (H_ - 1);
    int t = idx >> 10;
    int base = t * D_ + h * HD_;

    float s1 = sin_t[t * HD_ + d];
    float c1 = cos_t[t * HD_ + d];
    float s2 = sin_t[t * HD_ + d + 64];
    float c2 = cos_t[t * HD_ + d + 64];

    float q1 = Q[base + d];
    float q2 = Q[base + d + 64];
    Q[base + d]      = q1 * c1 - q2 * s1;
    Q[base + d + 64] = q2 * c2 + q1 * s2;

    float k1 = K[base + d];
    float k2 = K[base + d + 64];
    K[base + d]      = k1 * c1 - k2 * s1;
    K[base + d + 64] = k2 * c2 + k1 * s2;
}

// ---------------------------------------------------------------------------
// Flash-style attention with causal + same-doc mask.
// Epilogue writes bf16 hi/lo directly (feeds O-proj GEMM).
// ---------------------------------------------------------------------------
#define BM 64
#define BN 64
#define LDK 132
#define LDP 65

__global__ __launch_bounds__(256) void attn_kernel(const float* __restrict__ Q,
                                                   const float* __restrict__ K,
                                                   const float* __restrict__ V,
                                                   const int* __restrict__ doc,
                                                   bf16* __restrict__ Ahi,
                                                   bf16* __restrict__ Alo)
{
    extern __shared__ float sm[];
    float* Qs = sm;
    float* Ks = Qs + BM * HD_;
    float* Vs = Ks + BN * LDK;
    float* Ps = Vs + BN * HD_;
    float* rescale = Ps + BM * LDP;
    float* lrow = rescale + BM;
    __shared__ int qdoc[BM];
    __shared__ int kdoc[BN];

    const int h = blockIdx.y;
    const int qt = blockIdx.x;
    const int qbase = qt * BM;
    const int tid = threadIdx.x;

    const float scale = 0.08838834764831845f;

    for (int i = tid; i < BM * HD_ / 4; i += 256) {
        int r = i >> 5;
        int c4 = (i & 31) << 2;
        float4 v = *(const float4*)&Q[(qbase + r) * D_ + h * HD_ + c4];
        v.x *= scale; v.y *= scale; v.z *= scale; v.w *= scale;
        *(float4*)&Qs[r * HD_ + c4] = v;
    }
    if (tid < BM) qdoc[tid] = doc[qbase + tid];

    const int sr = tid >> 4;
    const int sc = tid & 15;
    const int rg = tid >> 4;
    const int c0 = (tid & 15) << 3;
    const int srow  = tid >> 2;   // softmax: 4 threads per row
    const int spart = tid & 3;

    float acc[4][8];
#pragma unroll
    for (int i = 0; i < 4; i++)
#pragma unroll
        for (int j = 0; j < 8; j++) acc[i][j] = 0.0f;

    float m_i = -1e30f, l_i = 0.0f;   // replicated x4 per row

    __syncthreads();
    const int qd_first = qdoc[0];

    for (int kt = 0; kt <= qt; ++kt) {
        const int kbase = kt * BN;
        if (doc[kbase + BN - 1] < qd_first) continue;

        __syncthreads();

        for (int i = tid; i < BN * HD_ / 4; i += 256) {
            int r = i >> 5;
            int c4 = (i & 31) << 2;
            float4 kv = *(const float4*)&K[(kbase + r) * D_ + h * HD_ + c4];
            float4 vv = *(const float4*)&V[(kbase + r) * D_ + h * HD_ + c4];
            *(float4*)&Ks[r * LDK + c4] = kv;
            *(float4*)&Vs[r * HD_ + c4] = vv;
        }
        if (tid < BN) kdoc[tid] = doc[kbase + tid];
        __syncthreads();

        float s[4][4];
#pragma unroll
        for (int i = 0; i < 4; i++)
#pragma unroll
            for (int j = 0; j < 4; j++) s[i][j] = 0.0f;

        for (int d4 = 0; d4 < HD_; d4 += 4) {
            float4 qv[4], kv[4];
#pragma unroll
            for (int i = 0; i < 4; i++)
                qv[i] = *(float4*)&Qs[(sr + 16 * i) * HD_ + d4];
#pragma unroll
            for (int j = 0; j < 4; j++)
                kv[j] = *(float4*)&Ks[(sc + 16 * j) * LDK + d4];
#pragma unroll
            for (int i = 0; i < 4; i++)
#pragma unroll
                for (int j = 0; j < 4; j++) {
                    s[i][j] = fmaf(qv[i].x, kv[j].x, s[i][j]);
                    s[i][j] = fmaf(qv[i].y, kv[j].y, s[i][j]);
                    s[i][j] = fmaf(qv[i].z, kv[j].z, s[i][j]);
                    s[i][j] = fmaf(qv[i].w, kv[j].w, s[i][j]);
                }
        }

#pragma unroll
        for (int i = 0; i < 4; i++) {
            int r = sr + 16 * i;
            int gq = qbase + r;
            int dq = qdoc[r];
#pragma unroll
            for (int j = 0; j < 4; j++) {
                int c = sc + 16 * j;
                int gk = kbase + c;
                bool ok = (gk <= gq) && (kdoc[c] == dq);
                Ps[r * LDP + c] = ok ? s[i][j] : -1e30f;
            }
        }
        __syncthreads();

        // Online softmax: 4 threads per row, shuffle-combined.
        {
            float* prow = &Ps[srow * LDP + spart * 16];
            float mrow = -1e30f;
#pragma unroll
            for (int j = 0; j < 16; j++) mrow = fmaxf(mrow, prow[j]);
            mrow = fmaxf(mrow, __shfl_xor_sync(0xffffffffu, mrow, 1));
            mrow = fmaxf(mrow, __shfl_xor_sync(0xffffffffu, mrow, 2));
            float mnew = fmaxf(m_i, mrow);
            float resc = __expf(m_i - mnew);
            float sum = 0.0f;
#pragma unroll
            for (int j = 0; j < 16; j++) {
                float sv = prow[j];
                float p = (sv <= -1e29f) ? 0.0f : __expf(sv - mnew);
                prow[j] = p;
                sum += p;
            }
            sum += __shfl_xor_sync(0xffffffffu, sum, 1);
            sum += __shfl_xor_sync(0xffffffffu, sum, 2);
            l_i = l_i * resc + sum;
            m_i = mnew;
            if (spart == 0) rescale[srow] = resc;
        }
        __syncthreads();

#pragma unroll
        for (int i = 0; i < 4; i++) {
            float resc = rescale[rg + 16 * i];
#pragma unroll
            for (int j = 0; j < 8; j++) acc[i][j] *= resc;
        }

        for (int j = 0; j < BN; ++j) {
            float4 v0 = *(float4*)&Vs[j * HD_ + c0];
            float4 v1 = *(float4*)&Vs[j * HD_ + c0 + 4];
#pragma unroll
            for (int i = 0; i < 4; i++) {
                float p = Ps[(rg + 16 * i) * LDP + j];
                acc[i][0] = fmaf(p, v0.x, acc[i][0]);
                acc[i][1] = fmaf(p, v0.y, acc[i][1]);
                acc[i][2] = fmaf(p, v0.z, acc[i][2]);
                acc[i][3] = fmaf(p, v0.w, acc[i][3]);
                acc[i][4] = fmaf(p, v1.x, acc[i][4]);
                acc[i][5] = fmaf(p, v1.y, acc[i][5]);
                acc[i][6] = fmaf(p, v1.z, acc[i][6]);
                acc[i][7] = fmaf(p, v1.w, acc[i][7]);
            }
        }
    }

    if (spart == 0) lrow[srow] = l_i;
    __syncthreads();

    // Epilogue: normalize and write split-bf16 directly.
#pragma unroll
    for (int i = 0; i < 4; i++) {
        int r = rg + 16 * i;
        float inv = 1.0f / lrow[r];
        bf16 h8[8], l8[8];
#pragma unroll
        for (int j = 0; j < 8; j++) {
            float v = acc[i][j] * inv;
            bf16 hv = __float2bfloat16(v);
            h8[j] = hv;
            l8[j] = __float2bfloat16(v - __bfloat162float(hv));
        }
        size_t idx = (size_t)(qbase + r) * D_ + h * HD_ + c0;
        *(uint4*)&Ahi[idx] = *(uint4*)h8;
        *(uint4*)&Alo[idx] = *(uint4*)l8;
    }
}

// ---------------------------------------------------------------------------
// Launch
// ---------------------------------------------------------------------------
extern "C" void kernel_launch(void* const* d_in, const int* in_sizes, int n_in,
                              void* d_out, int out_size)
{
    const float* x    = (const float*)d_in[0];
    const float* Wq   = (const float*)d_in[1];
    const float* Wk   = (const float*)d_in[2];
    const float* Wv   = (const float*)d_in[3];
    const float* Wo   = (const float*)d_in[4];
    const float* sint = (const float*)d_in[5];
    const float* cost = (const float*)d_in[6];
    const int*   doc  = (const int*)d_in[7];

    float *Q, *K, *V;
    bf16 *xhi, *xlo, *Ahi, *Alo, *Wthi, *Wtlo;
    cudaGetSymbolAddress((void**)&Q, g_Q);
    cudaGetSymbolAddress((void**)&K, g_K);
    cudaGetSymbolAddress((void**)&V, g_V);
    cudaGetSymbolAddress((void**)&xhi, g_xhi);
    cudaGetSymbolAddress((void**)&xlo, g_xlo);
    cudaGetSymbolAddress((void**)&Ahi, g_Ahi);
    cudaGetSymbolAddress((void**)&Alo, g_Alo);
    cudaGetSymbolAddress((void**)&Wthi, g_Wthi);
    cudaGetSymbolAddress((void**)&Wtlo, g_Wtlo);

    const size_t WSZ = (size_t)D_ * D_;
    const int NELEM = T_ * D_;

    split_kernel<<<(NELEM + 255) / 256, 256>>>(x, xhi, xlo);
    dim3 tsGrid(D_ / 32, D_ / 32, 4), tsBlk(32, 8);
    transpose_split4<<<tsGrid, tsBlk>>>(Wq, Wk, Wv, Wo, Wthi, Wtlo);

    cudaFuncSetAttribute(gemm_hmma,
                         cudaFuncAttributeMaxDynamicSharedMemorySize, GSMEM_BYTES);

    dim3 gGridQKV(D_ / 128, T_ / 128, 3);
    gemm_hmma<<<gGridQKV, 256, GSMEM_BYTES>>>(xhi, xlo, Wthi, Wtlo, Q, K, V);

    int nrope = T_ * H_ * 64;
    rope_kernel<<<(nrope + 255) / 256, 256>>>(Q, K, sint, cost);

    size_t smem = (size_t)(BM * HD_ + BN * LDK + BN * HD_ + BM * LDP + 2 * BM)
                  * sizeof(float);
    cudaFuncSetAttribute(attn_kernel,
                         cudaFuncAttributeMaxDynamicSharedMemorySize, (int)smem);
    attn_kernel<<<dim3(T_ / BM, H_), 256, smem>>>(Q, K, V, doc, Ahi, Alo);

    dim3 gGridO(D_ / 128, T_ / 128, 1);
    gemm_hmma<<<gGridO, 256, GSMEM_BYTES>>>(Ahi, Alo, Wthi + 3 * WSZ, Wtlo + 3 * WSZ,
                                            (float*)d_out, nullptr, nullptr);
}

// round 7
// speedup vs baseline: 1.7527x; 1.1371x over previous
#include <cuda_runtime.h>
#include <cuda_bf16.h>
#include <cstdint>
#include <math.h>

#define T_  2048
#define D_  2048
#define H_  16
#define HD_ 128

typedef __nv_bfloat16 bf16;

// ---------------------------------------------------------------------------
// Scratch (allocation-free rule: __device__ globals)
// ---------------------------------------------------------------------------
__device__ float g_Q[T_ * D_];
__device__ float g_K[T_ * D_];
__device__ float g_V[T_ * D_];
__device__ bf16 g_xhi[T_ * D_];
__device__ bf16 g_xlo[T_ * D_];
__device__ bf16 g_Ahi[T_ * D_];
__device__ bf16 g_Alo[T_ * D_];
__device__ bf16 g_Qhi[T_ * D_];
__device__ bf16 g_Qlo[T_ * D_];
__device__ bf16 g_Khi[T_ * D_];
__device__ bf16 g_Klo[T_ * D_];
__device__ bf16 g_Vhi[T_ * D_];
__device__ bf16 g_Vlo[T_ * D_];
__device__ bf16 g_Wthi[4][D_ * D_];   // transposed weights [N,K], hi part
__device__ bf16 g_Wtlo[4][D_ * D_];   // transposed weights [N,K], lo part

// ---------------------------------------------------------------------------
// PTX helpers (compute_103-safe: mma.sync / ldmatrix / cp.async only)
// ---------------------------------------------------------------------------
__device__ __forceinline__ uint32_t smem_u32(const void* p) {
    uint32_t a;
    asm("{ .reg .u64 t; cvta.to.shared.u64 t, %1; cvt.u32.u64 %0, t; }"
        : "=r"(a) : "l"(p));
    return a;
}

#define CPA16(dst, src) \
    asm volatile("cp.async.cg.shared.global [%0], [%1], 16;" :: "r"(dst), "l"(src) : "memory")
#define CPA_COMMIT() asm volatile("cp.async.commit_group;" ::: "memory")
#define CPA_WAIT(n)  asm volatile("cp.async.wait_group %0;" :: "n"(n) : "memory")

__device__ __forceinline__ void ldsm_x4(uint32_t* r, uint32_t addr) {
    asm volatile("ldmatrix.sync.aligned.m8n8.x4.shared.b16 {%0,%1,%2,%3}, [%4];"
                 : "=r"(r[0]), "=r"(r[1]), "=r"(r[2]), "=r"(r[3]) : "r"(addr));
}

__device__ __forceinline__ void ldsm_x4_t(uint32_t* r, uint32_t addr) {
    asm volatile("ldmatrix.sync.aligned.m8n8.x4.trans.shared.b16 {%0,%1,%2,%3}, [%4];"
                 : "=r"(r[0]), "=r"(r[1]), "=r"(r[2]), "=r"(r[3]) : "r"(addr));
}

__device__ __forceinline__ void mma_bf16(float* d, const uint32_t* a,
                                         const uint32_t* b) {
    asm volatile(
        "mma.sync.aligned.m16n8k16.row.col.f32.bf16.bf16.f32 "
        "{%0,%1,%2,%3}, {%4,%5,%6,%7}, {%8,%9}, {%0,%1,%2,%3};"
        : "+f"(d[0]), "+f"(d[1]), "+f"(d[2]), "+f"(d[3])
        : "r"(a[0]), "r"(a[1]), "r"(a[2]), "r"(a[3]), "r"(b[0]), "r"(b[1]));
}

// pack two fp32 -> bf16x2 register (lo = first element)
__device__ __forceinline__ uint32_t packbf(float lo, float hi) {
    uint32_t r;
    asm("cvt.rn.bf16x2.f32 %0, %1, %2;" : "=r"(r) : "f"(hi), "f"(lo));
    return r;
}

__device__ __forceinline__ float bfround(float v) {
    return __bfloat162float(__float2bfloat16(v));
}

// ---------------------------------------------------------------------------
// Split fp32 -> (hi, lo) bf16, row-major
// ---------------------------------------------------------------------------
__global__ __launch_bounds__(256) void split_kernel(const float* __restrict__ src,
                                                    bf16* __restrict__ hi,
                                                    bf16* __restrict__ lo)
{
    int i = blockIdx.x * 256 + threadIdx.x;
    if (i >= T_ * D_) return;
    float v = src[i];
    bf16 h = __float2bfloat16(v);
    float r = v - __bfloat162float(h);
    hi[i] = h;
    lo[i] = __float2bfloat16(r);
}

// ---------------------------------------------------------------------------
// Transpose + split all 4 weights in one launch: W[K,N] -> Thi/Tlo[N,K].
// ---------------------------------------------------------------------------
__global__ __launch_bounds__(256) void transpose_split4(
    const float* __restrict__ W0, const float* __restrict__ W1,
    const float* __restrict__ W2, const float* __restrict__ W3,
    bf16* __restrict__ ThiB, bf16* __restrict__ TloB)
{
    __shared__ float tile[32][33];
    const size_t WSZ = (size_t)D_ * D_;
    int z = blockIdx.z;
    const float* W = (z == 0) ? W0 : (z == 1) ? W1 : (z == 2) ? W2 : W3;
    bf16* Thi = ThiB + z * WSZ;
    bf16* Tlo = TloB + z * WSZ;

    int bx = blockIdx.x * 32;
    int by = blockIdx.y * 32;
    int tx = threadIdx.x;
    int ty = threadIdx.y;
#pragma unroll
    for (int j = 0; j < 32; j += 8)
        tile[ty + j][tx] = W[(size_t)(by + ty + j) * D_ + bx + tx];
    __syncthreads();
#pragma unroll
    for (int j = 0; j < 32; j += 8) {
        float v = tile[tx][ty + j];
        bf16 h = __float2bfloat16(v);
        float r = v - __bfloat162float(h);
        size_t o = (size_t)(bx + ty + j) * D_ + by + tx;
        Thi[o] = h;
        Tlo[o] = __float2bfloat16(r);
    }
}

// ---------------------------------------------------------------------------
// HMMA GEMM: C = A @ Bt^T, split-bf16 3-MMA. CTA tile 128x128, BK=64,
// 3-stage cp.async, single-sync-per-chunk pipeline (prefetch distance 2).
// ---------------------------------------------------------------------------
#define STAGE_BYTES 65536
#define GSMEM_BYTES (3 * STAGE_BYTES)

__global__ __launch_bounds__(256) void gemm_hmma(
    const bf16* __restrict__ Ahi, const bf16* __restrict__ Alo,
    const bf16* __restrict__ Bhi_base, const bf16* __restrict__ Blo_base,
    float* C0, float* C1, float* C2)
{
    extern __shared__ char smem[];
    uint32_t sb = smem_u32(smem);
    const int tid  = threadIdx.x;
    const int wid  = tid >> 5;
    const int lane = tid & 31;
    const int wm = wid >> 2;
    const int wn = wid & 3;
    const int row0 = blockIdx.y * 128;
    const int col0 = blockIdx.x * 128;
    const size_t WSZ = (size_t)D_ * D_;
    const bf16* Bhi = Bhi_base + blockIdx.z * WSZ;
    const bf16* Blo = Blo_base + blockIdx.z * WSZ;
    float* C = (blockIdx.z == 0) ? C0 : (blockIdx.z == 1) ? C1 : C2;

    const char* base[4] = {
        (const char*)(Ahi + (size_t)row0 * D_),
        (const char*)(Alo + (size_t)row0 * D_),
        (const char*)(Bhi + (size_t)col0 * D_),
        (const char*)(Blo + (size_t)col0 * D_)
    };

    auto load_stage = [&](int c, int s) {
        uint32_t st = sb + s * STAGE_BYTES;
#pragma unroll
        for (int j = 0; j < 16; j++) {
            int m = j >> 2;
            int rem = tid + ((j & 3) << 8);
            int r = rem >> 3;
            int cb = (rem & 7) << 4;
            const char* src = base[m] + (size_t)r * (D_ * 2) + c * 128 + cb;
            uint32_t off = (uint32_t)(r * 128) + (cb ^ ((r & 7) << 4));
            CPA16(st + m * 16384 + off, src);
        }
        CPA_COMMIT();
    };

    float acc[4][4][4];
#pragma unroll
    for (int i = 0; i < 4; i++)
#pragma unroll
        for (int j = 0; j < 4; j++)
#pragma unroll
            for (int q = 0; q < 4; q++) acc[i][j][q] = 0.0f;

    load_stage(0, 0);
    load_stage(1, 1);

    for (int c = 0; c < 32; c++) {
        if (c < 31) CPA_WAIT(1);
        else        CPA_WAIT(0);
        __syncthreads();
        if (c + 2 < 32) load_stage(c + 2, (c + 2) % 3);

        uint32_t st   = sb + (c % 3) * STAGE_BYTES;
        uint32_t sAhi = st;
        uint32_t sAlo = st + 16384;
        uint32_t sBhi = st + 32768;
        uint32_t sBlo = st + 49152;

#pragma unroll
        for (int ks = 0; ks < 4; ks++) {
            uint32_t ah[4][4], al[4][4];
#pragma unroll
            for (int i = 0; i < 4; i++) {
                int row = wm * 64 + i * 16 + (lane & 15);
                uint32_t colb = ks * 32 + ((lane >> 4) & 1) * 16;
                uint32_t off = (uint32_t)(row * 128) + (colb ^ ((row & 7) << 4));
                ldsm_x4(ah[i], sAhi + off);
                ldsm_x4(al[i], sAlo + off);
            }
            uint32_t bh[8], bl[8];
#pragma unroll
            for (int jp = 0; jp < 2; jp++) {
                int row = wn * 32 + jp * 16 + ((lane >> 4) & 1) * 8 + (lane & 7);
                uint32_t colb = ks * 32 + ((lane >> 3) & 1) * 16;
                uint32_t off = (uint32_t)(row * 128) + (colb ^ ((row & 7) << 4));
                ldsm_x4(&bh[jp * 4], sBhi + off);
                ldsm_x4(&bl[jp * 4], sBlo + off);
            }
#pragma unroll
            for (int i = 0; i < 4; i++)
#pragma unroll
                for (int j = 0; j < 4; j++) {
                    mma_bf16(acc[i][j], ah[i], &bh[j * 2]);
                    mma_bf16(acc[i][j], al[i], &bh[j * 2]);
                    mma_bf16(acc[i][j], ah[i], &bl[j * 2]);
                }
        }
    }

    const int g = lane >> 2;
    const int t = lane & 3;
#pragma unroll
    for (int i = 0; i < 4; i++) {
#pragma unroll
        for (int j = 0; j < 4; j++) {
            int row = row0 + wm * 64 + i * 16 + g;
            int col = col0 + wn * 32 + j * 8 + 2 * t;
            *(float2*)&C[(size_t)row * D_ + col] =
                make_float2(acc[i][j][0], acc[i][j][1]);
            *(float2*)&C[(size_t)(row + 8) * D_ + col] =
                make_float2(acc[i][j][2], acc[i][j][3]);
        }
    }
}

// ---------------------------------------------------------------------------
// RoPE + split: read fp32 Q,K,V; apply rope to Q,K; write all as split bf16.
// ---------------------------------------------------------------------------
__global__ __launch_bounds__(256) void rope_split(
    const float* __restrict__ Q, const float* __restrict__ K,
    const float* __restrict__ V,
    const float* __restrict__ sin_t, const float* __restrict__ cos_t,
    bf16* __restrict__ Qhi, bf16* __restrict__ Qlo,
    bf16* __restrict__ Khi, bf16* __restrict__ Klo,
    bf16* __restrict__ Vhi, bf16* __restrict__ Vlo)
{
    int idx = blockIdx.x * blockDim.x + threadIdx.x;
    if (idx >= T_ * H_ * 64) return;
    int d = idx & 63;
    int h = (idx >> 6) & (H_ - 1);
    int t = idx >> 10;
    int base = t * D_ + h * HD_;

    float s1 = sin_t[t * HD_ + d];
    float c1 = cos_t[t * HD_ + d];
    float s2 = sin_t[t * HD_ + d + 64];
    float c2 = cos_t[t * HD_ + d + 64];

    float q1 = Q[base + d], q2 = Q[base + d + 64];
    float qo1 = q1 * c1 - q2 * s1;
    float qo2 = q2 * c2 + q1 * s2;
    float k1 = K[base + d], k2 = K[base + d + 64];
    float ko1 = k1 * c1 - k2 * s1;
    float ko2 = k2 * c2 + k1 * s2;
    float v1 = V[base + d], v2 = V[base + d + 64];

    float r;
    r = bfround(qo1); Qhi[base + d]      = __float2bfloat16(qo1); Qlo[base + d]      = __float2bfloat16(qo1 - r);
    r = bfround(qo2); Qhi[base + d + 64] = __float2bfloat16(qo2); Qlo[base + d + 64] = __float2bfloat16(qo2 - r);
    r = bfround(ko1); Khi[base + d]      = __float2bfloat16(ko1); Klo[base + d]      = __float2bfloat16(ko1 - r);
    r = bfround(ko2); Khi[base + d + 64] = __float2bfloat16(ko2); Klo[base + d + 64] = __float2bfloat16(ko2 - r);
    r = bfround(v1);  Vhi[base + d]      = __float2bfloat16(v1);  Vlo[base + d]      = __float2bfloat16(v1 - r);
    r = bfround(v2);  Vhi[base + d + 64] = __float2bfloat16(v2);  Vlo[base + d + 64] = __float2bfloat16(v2 - r);
}

// ---------------------------------------------------------------------------
// HMMA flash attention with causal + same-doc mask. Split-bf16 3-term MMA
// for both S=QK^T and P@V. BM=128 q rows, BN=64 kv rows, 8 warps x 16 rows.
// Writes split-bf16 output directly (feeds O-proj GEMM).
// ---------------------------------------------------------------------------
#define BMA 128
#define BNA 64
#define ASMEM_BYTES 131072

__global__ __launch_bounds__(256, 1) void attn_hmma(
    const bf16* __restrict__ Qhi, const bf16* __restrict__ Qlo,
    const bf16* __restrict__ Khi, const bf16* __restrict__ Klo,
    const bf16* __restrict__ Vhi, const bf16* __restrict__ Vlo,
    const int* __restrict__ doc,
    bf16* __restrict__ Ahi, bf16* __restrict__ Alo)
{
    extern __shared__ char smem[];
    const uint32_t sQh = smem_u32(smem);
    const uint32_t sQl = sQh + 32768;
    const uint32_t sKh = sQh + 65536;
    const uint32_t sKl = sQh + 81920;
    const uint32_t sVh = sQh + 98304;
    const uint32_t sVl = sQh + 114688;
    __shared__ int qdoc[BMA];
    __shared__ int kdoc[BNA];

    const int h = blockIdx.y;
    const int qt = blockIdx.x;
    const int qbase = qt * BMA;
    const int tid = threadIdx.x;
    const int wid = tid >> 5;
    const int lane = tid & 31;
    const int g = lane >> 2;
    const int t = lane & 3;
    const int r0 = wid * 16;
    const float scale = 0.08838834764831845f;

    // Load Q tiles (hi, lo) swizzled: 256B rows, XOR within 128B halves.
    for (int i = tid; i < BMA * 16; i += 256) {
        int r = i >> 4;
        int cb = (i & 15) << 4;
        size_t gidx = (size_t)(qbase + r) * D_ + h * HD_ + (cb >> 1);
        uint32_t off = (uint32_t)(r * 256) + (cb ^ ((r & 7) << 4));
        *(uint4*)(smem + off)         = *(const uint4*)&Qhi[gidx];
        *(uint4*)(smem + 32768 + off) = *(const uint4*)&Qlo[gidx];
    }
    if (tid < BMA) qdoc[tid] = doc[qbase + tid];
    __syncthreads();

    float oacc[16][4];
#pragma unroll
    for (int nt = 0; nt < 16; nt++)
#pragma unroll
        for (int q = 0; q < 4; q++) oacc[nt][q] = 0.0f;

    float m0 = -1e30f, m1 = -1e30f, l0 = 0.0f, l1 = 0.0f;
    const int qd_first = qdoc[0];
    const int qr0 = qbase + r0 + g;
    const int qr1 = qr0 + 8;
    const int dq0 = qdoc[r0 + g];
    const int dq1 = qdoc[r0 + g + 8];

    const int ktmax = 2 * qt + 1;
    for (int kt = 0; kt <= ktmax; kt++) {
        const int kbase = kt * BNA;
        if (doc[kbase + BNA - 1] < qd_first) continue;

        __syncthreads();
        for (int i = tid; i < BNA * 16; i += 256) {
            int r = i >> 4;
            int cb = (i & 15) << 4;
            size_t gidx = (size_t)(kbase + r) * D_ + h * HD_ + (cb >> 1);
            uint32_t off = (uint32_t)(r * 256) + (cb ^ ((r & 7) << 4));
            *(uint4*)(smem + 65536 + off)  = *(const uint4*)&Khi[gidx];
            *(uint4*)(smem + 81920 + off)  = *(const uint4*)&Klo[gidx];
            *(uint4*)(smem + 98304 + off)  = *(const uint4*)&Vhi[gidx];
            *(uint4*)(smem + 114688 + off) = *(const uint4*)&Vlo[gidx];
        }
        if (tid < BNA) kdoc[tid] = doc[kbase + tid];
        __syncthreads();

        // --- S = Q K^T (3-term split) ---
        float sacc[8][4];
#pragma unroll
        for (int nt = 0; nt < 8; nt++)
#pragma unroll
            for (int q = 0; q < 4; q++) sacc[nt][q] = 0.0f;

#pragma unroll
        for (int ks = 0; ks < 8; ks++) {
            uint32_t qh[4], ql[4];
            {
                int row = r0 + (lane & 15);
                int cb = ks * 32 + ((lane >> 4) & 1) * 16;
                uint32_t off = (uint32_t)(row * 256) + (cb ^ ((row & 7) << 4));
                ldsm_x4(qh, sQh + off);
                ldsm_x4(ql, sQl + off);
            }
#pragma unroll
            for (int jp = 0; jp < 4; jp++) {
                uint32_t kh[4], kl[4];
                int row = jp * 16 + ((lane >> 4) & 1) * 8 + (lane & 7);
                int cb = ks * 32 + ((lane >> 3) & 1) * 16;
                uint32_t off = (uint32_t)(row * 256) + (cb ^ ((row & 7) << 4));
                ldsm_x4(kh, sKh + off);
                ldsm_x4(kl, sKl + off);
                mma_bf16(sacc[2 * jp],     qh, &kh[0]);
                mma_bf16(sacc[2 * jp],     ql, &kh[0]);
                mma_bf16(sacc[2 * jp],     qh, &kl[0]);
                mma_bf16(sacc[2 * jp + 1], qh, &kh[2]);
                mma_bf16(sacc[2 * jp + 1], ql, &kh[2]);
                mma_bf16(sacc[2 * jp + 1], qh, &kl[2]);
            }
        }

        // --- scale + mask ---
#pragma unroll
        for (int nt = 0; nt < 8; nt++) {
#pragma unroll
            for (int e = 0; e < 2; e++) {
                int col = nt * 8 + 2 * t + e;
                int kc = kbase + col;
                int kd = kdoc[col];
                float v0 = sacc[nt][e] * scale;
                float v1 = sacc[nt][2 + e] * scale;
                sacc[nt][e]     = (kc <= qr0 && kd == dq0) ? v0 : -1e30f;
                sacc[nt][2 + e] = (kc <= qr1 && kd == dq1) ? v1 : -1e30f;
            }
        }

        // --- online softmax (2 rows per thread, quad-replicated) ---
        float mr0 = -1e30f, mr1 = -1e30f;
#pragma unroll
        for (int nt = 0; nt < 8; nt++) {
            mr0 = fmaxf(mr0, fmaxf(sacc[nt][0], sacc[nt][1]));
            mr1 = fmaxf(mr1, fmaxf(sacc[nt][2], sacc[nt][3]));
        }
        mr0 = fmaxf(mr0, __shfl_xor_sync(0xffffffffu, mr0, 1));
        mr0 = fmaxf(mr0, __shfl_xor_sync(0xffffffffu, mr0, 2));
        mr1 = fmaxf(mr1, __shfl_xor_sync(0xffffffffu, mr1, 1));
        mr1 = fmaxf(mr1, __shfl_xor_sync(0xffffffffu, mr1, 2));
        float mn0 = fmaxf(m0, mr0), mn1 = fmaxf(m1, mr1);
        float rs0 = __expf(m0 - mn0), rs1 = __expf(m1 - mn1);
        float s0 = 0.0f, s1 = 0.0f;
#pragma unroll
        for (int nt = 0; nt < 8; nt++) {
#pragma unroll
            for (int e = 0; e < 2; e++) {
                float a = sacc[nt][e];
                a = (a <= -1e29f) ? 0.0f : __expf(a - mn0);
                sacc[nt][e] = a; s0 += a;
                float b = sacc[nt][2 + e];
                b = (b <= -1e29f) ? 0.0f : __expf(b - mn1);
                sacc[nt][2 + e] = b; s1 += b;
            }
        }
        s0 += __shfl_xor_sync(0xffffffffu, s0, 1);
        s0 += __shfl_xor_sync(0xffffffffu, s0, 2);
        s1 += __shfl_xor_sync(0xffffffffu, s1, 1);
        s1 += __shfl_xor_sync(0xffffffffu, s1, 2);
        l0 = l0 * rs0 + s0; m0 = mn0;
        l1 = l1 * rs1 + s1; m1 = mn1;

#pragma unroll
        for (int nt = 0; nt < 16; nt++) {
            oacc[nt][0] *= rs0; oacc[nt][1] *= rs0;
            oacc[nt][2] *= rs1; oacc[nt][3] *= rs1;
        }

        // --- O += P V (3-term split; P frags built in registers) ---
#pragma unroll
        for (int ks = 0; ks < 4; ks++) {
            float p00 = sacc[2 * ks][0],     p01 = sacc[2 * ks][1];
            float p02 = sacc[2 * ks][2],     p03 = sacc[2 * ks][3];
            float p10 = sacc[2 * ks + 1][0], p11 = sacc[2 * ks + 1][1];
            float p12 = sacc[2 * ks + 1][2], p13 = sacc[2 * ks + 1][3];
            uint32_t phi[4], plo[4];
            phi[0] = packbf(p00, p01); phi[1] = packbf(p02, p03);
            phi[2] = packbf(p10, p11); phi[3] = packbf(p12, p13);
            plo[0] = packbf(p00 - bfround(p00), p01 - bfround(p01));
            plo[1] = packbf(p02 - bfround(p02), p03 - bfround(p03));
            plo[2] = packbf(p10 - bfround(p10), p11 - bfround(p11));
            plo[3] = packbf(p12 - bfround(p12), p13 - bfround(p13));

#pragma unroll
            for (int n0 = 0; n0 < 128; n0 += 16) {
                uint32_t vh[4], vl[4];
                int row = ks * 16 + ((lane >> 3) & 1) * 8 + (lane & 7);
                int cb = n0 * 2 + ((lane >> 4) & 1) * 16;
                uint32_t off = (uint32_t)(row * 256) + (cb ^ ((row & 7) << 4));
                ldsm_x4_t(vh, sVh + off);
                ldsm_x4_t(vl, sVl + off);
                int nt = n0 >> 3;
                mma_bf16(oacc[nt],     phi, &vh[0]);
                mma_bf16(oacc[nt],     plo, &vh[0]);
                mma_bf16(oacc[nt],     phi, &vl[0]);
                mma_bf16(oacc[nt + 1], phi, &vh[2]);
                mma_bf16(oacc[nt + 1], plo, &vh[2]);
                mma_bf16(oacc[nt + 1], phi, &vl[2]);
            }
        }
    }

    // --- epilogue: normalize, split-bf16 write ---
    float i0 = 1.0f / l0, i1 = 1.0f / l1;
#pragma unroll
    for (int nt = 0; nt < 16; nt++) {
        float v0 = oacc[nt][0] * i0, v1 = oacc[nt][1] * i0;
        float v2 = oacc[nt][2] * i1, v3 = oacc[nt][3] * i1;
        size_t idx0 = (size_t)qr0 * D_ + h * HD_ + nt * 8 + 2 * t;
        size_t idx1 = idx0 + (size_t)8 * D_;
        *(uint32_t*)&Ahi[idx0] = packbf(v0, v1);
        *(uint32_t*)&Alo[idx0] = packbf(v0 - bfround(v0), v1 - bfround(v1));
        *(uint32_t*)&Ahi[idx1] = packbf(v2, v3);
        *(uint32_t*)&Alo[idx1] = packbf(v2 - bfround(v2), v3 - bfround(v3));
    }
}

// ---------------------------------------------------------------------------
// Launch
// ---------------------------------------------------------------------------
extern "C" void kernel_launch(void* const* d_in, const int* in_sizes, int n_in,
                              void* d_out, int out_size)
{
    const float* x    = (const float*)d_in[0];
    const float* Wq   = (const float*)d_in[1];
    const float* Wk   = (const float*)d_in[2];
    const float* Wv   = (const float*)d_in[3];
    const float* Wo   = (const float*)d_in[4];
    const float* sint = (const float*)d_in[5];
    const float* cost = (const float*)d_in[6];
    const int*   doc  = (const int*)d_in[7];

    float *Q, *K, *V;
    bf16 *xhi, *xlo, *Ahi, *Alo, *Wthi, *Wtlo;
    bf16 *Qhi, *Qlo, *Khi, *Klo, *Vhi, *Vlo;
    cudaGetSymbolAddress((void**)&Q, g_Q);
    cudaGetSymbolAddress((void**)&K, g_K);
    cudaGetSymbolAddress((void**)&V, g_V);
    cudaGetSymbolAddress((void**)&xhi, g_xhi);
    cudaGetSymbolAddress((void**)&xlo, g_xlo);
    cudaGetSymbolAddress((void**)&Ahi, g_Ahi);
    cudaGetSymbolAddress((void**)&Alo, g_Alo);
    cudaGetSymbolAddress((void**)&Qhi, g_Qhi);
    cudaGetSymbolAddress((void**)&Qlo, g_Qlo);
    cudaGetSymbolAddress((void**)&Khi, g_Khi);
    cudaGetSymbolAddress((void**)&Klo, g_Klo);
    cudaGetSymbolAddress((void**)&Vhi, g_Vhi);
    cudaGetSymbolAddress((void**)&Vlo, g_Vlo);
    cudaGetSymbolAddress((void**)&Wthi, g_Wthi);
    cudaGetSymbolAddress((void**)&Wtlo, g_Wtlo);

    const size_t WSZ = (size_t)D_ * D_;
    const int NELEM = T_ * D_;

    split_kernel<<<(NELEM + 255) / 256, 256>>>(x, xhi, xlo);
    dim3 tsGrid(D_ / 32, D_ / 32, 4), tsBlk(32, 8);
    transpose_split4<<<tsGrid, tsBlk>>>(Wq, Wk, Wv, Wo, Wthi, Wtlo);

    cudaFuncSetAttribute(gemm_hmma,
                         cudaFuncAttributeMaxDynamicSharedMemorySize, GSMEM_BYTES);

    dim3 gGridQKV(D_ / 128, T_ / 128, 3);
    gemm_hmma<<<gGridQKV, 256, GSMEM_BYTES>>>(xhi, xlo, Wthi, Wtlo, Q, K, V);

    int nrope = T_ * H_ * 64;
    rope_split<<<(nrope + 255) / 256, 256>>>(Q, K, V, sint, cost,
                                             Qhi, Qlo, Khi, Klo, Vhi, Vlo);

    cudaFuncSetAttribute(attn_hmma,
                         cudaFuncAttributeMaxDynamicSharedMemorySize, ASMEM_BYTES);
    attn_hmma<<<dim3(T_ / BMA, H_), 256, ASMEM_BYTES>>>(
        Qhi, Qlo, Khi, Klo, Vhi, Vlo, doc, Ahi, Alo);

    dim3 gGridO(D_ / 128, T_ / 128, 1);
    gemm_hmma<<<gGridO, 256, GSMEM_BYTES>>>(Ahi, Alo, Wthi + 3 * WSZ, Wtlo + 3 * WSZ,
                                            (float*)d_out, nullptr, nullptr);
}